// round 10
// baseline (speedup 1.0000x reference)
#include <cuda_runtime.h>
#include <cuda_bf16.h>
#include <math.h>
#include <stdint.h>

#define BOX_P 32
#define PATCH_ELEMS (BOX_P * BOX_P)   // 1024
#define WARPS_PER_PATCH 4
#define ROWS_PER_WARP (BOX_P / WARPS_PER_PATCH)   // 8
#define WARPS_PER_CTA 8
#define PATCHES_PER_CTA (WARPS_PER_CTA / WARPS_PER_PATCH)  // 2
#define THREADS (WARPS_PER_CTA * 32)
#define EPSF 1e-6f

#define NBINS 4096          // 64x64 spatial tiles (64px granularity), Morton-ordered
#define MAX_CORR 32768

__device__ int g_perm[MAX_CORR];

// Morton interleave of 6-bit tile coords -> 2D-local bin ordering
__device__ __forceinline__ int patch_key(int x, int y) {
    const int a = (x >> 6) & 63, b = (y >> 6) & 63;
    int k = 0;
    #pragma unroll
    for (int i = 0; i < 6; i++)
        k |= (((a >> i) & 1) << (2 * i + 1)) | (((b >> i) & 1) << (2 * i));
    return k;
}

// ---- K1: fused hist + scan + scatter, ONE CTA, smem only ----
__global__ __launch_bounds__(1024)
void lp_sort_kernel(const int* __restrict__ x0,
                    const int* __restrict__ y0,
                    int n_corr, float* __restrict__ out)
{
    __shared__ int s_cnt[NBINS];   // 16 KB
    __shared__ int s_warp[32];

    const int t = threadIdx.x, lane = t & 31, w = t >> 5;
    if (t == 0) out[0] = 0.0f;

    // zero bins
    #pragma unroll
    for (int j = 0; j < NBINS / 1024; j++) s_cnt[t + j * 1024] = 0;
    __syncthreads();

    // histogram (coords pulled into L1/L2 here; scatter pass below re-hits them)
    for (int i = t; i < n_corr; i += 1024)
        atomicAdd(&s_cnt[patch_key(x0[i], y0[i])], 1);
    __syncthreads();

    // exclusive scan over 4096 bins (4 per thread + hierarchical shuffle scan)
    int c[4], tsum = 0;
    #pragma unroll
    for (int j = 0; j < 4; j++) { c[j] = s_cnt[t * 4 + j]; tsum += c[j]; }

    int incl = tsum;
    #pragma unroll
    for (int o = 1; o < 32; o <<= 1) {
        int v = __shfl_up_sync(0xFFFFFFFFu, incl, o);
        if (lane >= o) incl += v;
    }
    if (lane == 31) s_warp[w] = incl;
    __syncthreads();
    if (w == 0) {
        int v = s_warp[lane];
        #pragma unroll
        for (int o = 1; o < 32; o <<= 1) {
            int u = __shfl_up_sync(0xFFFFFFFFu, v, o);
            if (lane >= o) v += u;
        }
        s_warp[lane] = v;
    }
    __syncthreads();

    int run = ((w > 0) ? s_warp[w - 1] : 0) + incl - tsum;  // exclusive prefix
    __syncthreads();                 // all reads of s_cnt done before overwrite
    #pragma unroll
    for (int j = 0; j < 4; j++) { s_cnt[t * 4 + j] = run; run += c[j]; }
    __syncthreads();

    // scatter (coords L1-hot from the histogram pass)
    for (int i = t; i < n_corr; i += 1024) {
        const int pos = atomicAdd(&s_cnt[patch_key(x0[i], y0[i])], 1);
        g_perm[pos] = i;
    }
}

// ---- K2: main Pearson kernel (R5 structure + perm indirection) ----
__global__ __launch_bounds__(THREADS)
void lp_pearson_sorted_kernel(const float* __restrict__ pred,
                              const float* __restrict__ gt,
                              const int*   __restrict__ x0,
                              const int*   __restrict__ y0,
                              float* __restrict__ out,
                              int n_corr, int W)
{
    const int warp    = threadIdx.x >> 5;
    const int lane    = threadIdx.x & 31;
    const int plocal  = warp >> 2;
    const int quarter = warp & 3;
    const int slot = blockIdx.x * PATCHES_PER_CTA + plocal;
    const bool valid = (slot < n_corr);
    const int b = valid ? g_perm[slot] : 0;

    __shared__ float sh[WARPS_PER_CTA][5];

    float sp = 0.f, sg = 0.f, spp = 0.f, sgg = 0.f, spg = 0.f;

    if (valid) {
        const int X = x0[b] + quarter * ROWS_PER_WARP;
        const int Y = y0[b];
        const float* __restrict__ pbase = pred + (size_t)X * W + Y + lane;
        const float* __restrict__ gbase = gt   + (size_t)X * W + Y + lane;

        float p[ROWS_PER_WARP], g[ROWS_PER_WARP];
        #pragma unroll
        for (int r = 0; r < ROWS_PER_WARP; r++) {
            const size_t off = (size_t)r * W;
            p[r] = __ldg(pbase + off);
            g[r] = __ldg(gbase + off);
        }
        #pragma unroll
        for (int r = 0; r < ROWS_PER_WARP; r++) {
            sp  += p[r];
            sg  += g[r];
            spp += p[r] * p[r];
            sgg += g[r] * g[r];
            spg += p[r] * g[r];
        }
    }

    #pragma unroll
    for (int o = 16; o > 0; o >>= 1) {
        sp  += __shfl_down_sync(0xFFFFFFFFu, sp,  o);
        sg  += __shfl_down_sync(0xFFFFFFFFu, sg,  o);
        spp += __shfl_down_sync(0xFFFFFFFFu, spp, o);
        sgg += __shfl_down_sync(0xFFFFFFFFu, sgg, o);
        spg += __shfl_down_sync(0xFFFFFFFFu, spg, o);
    }

    if (lane == 0) {
        sh[warp][0] = sp;  sh[warp][1] = sg;  sh[warp][2] = spp;
        sh[warp][3] = sgg; sh[warp][4] = spg;
    }
    __syncthreads();

    if (quarter == 0 && lane == 0 && valid) {
        const int base = plocal * WARPS_PER_PATCH;
        float Sp = 0.f, Sg = 0.f, Spp = 0.f, Sgg = 0.f, Spg = 0.f;
        #pragma unroll
        for (int w = 0; w < WARPS_PER_PATCH; w++) {
            Sp  += sh[base + w][0];
            Sg  += sh[base + w][1];
            Spp += sh[base + w][2];
            Sgg += sh[base + w][3];
            Spg += sh[base + w][4];
        }

        const float P    = (float)PATCH_ELEMS;
        const float invP = 1.0f / P;
        const float mp = Sp * invP;
        const float mg = Sg * invP;
        // unbiased (ddof=1) variance, matching jnp.std(ddof=1)
        const float varp = (Spp - Sp * mp) / (P - 1.0f);
        const float varg = (Sgg - Sg * mg) / (P - 1.0f);
        const float sdp = sqrtf(fmaxf(varp, 0.f)) + EPSF;
        const float sdg = sqrtf(fmaxf(varg, 0.f)) + EPSF;
        const float cov = Spg - Sp * mg;   // = Spg - Sp*Sg/P
        const float co  = cov / (P * sdp * sdg);
        atomicAdd(out, (1.0f - co) / (float)n_corr);
    }
}

extern "C" void kernel_launch(void* const* d_in, const int* in_sizes, int n_in,
                              void* d_out, int out_size)
{
    const float* pred = (const float*)d_in[0];
    const float* gt   = (const float*)d_in[1];
    const int*   x0   = (const int*)d_in[2];
    const int*   y0   = (const int*)d_in[3];
    float* out = (float*)d_out;

    const int n_corr = in_sizes[2];

    // Derive W from the (square, C=1) image element count.
    int W = 1;
    while ((long long)W * W < (long long)in_sizes[0]) W <<= 1;

    lp_sort_kernel<<<1, 1024>>>(x0, y0, n_corr, out);

    const int grid = (n_corr + PATCHES_PER_CTA - 1) / PATCHES_PER_CTA;
    lp_pearson_sorted_kernel<<<grid, THREADS>>>(pred, gt, x0, y0, out, n_corr, W);
}

// round 11
// speedup vs baseline: 1.4508x; 1.4508x over previous
#include <cuda_runtime.h>
#include <cuda_bf16.h>
#include <math.h>

#define BOX_P 32
#define PATCH_ELEMS (BOX_P * BOX_P)   // 1024
#define WARPS_PER_PATCH 4
#define ROWS_PER_WARP (BOX_P / WARPS_PER_PATCH)   // 8
#define THREADS (WARPS_PER_PATCH * 32)             // 128: one patch per CTA
#define EPSF 1e-6f

__global__ void lp_zero_out(float* out) {
    if (threadIdx.x == 0) out[0] = 0.0f;
}

__global__ __launch_bounds__(THREADS)
void lp_pearson_kernel(const float* __restrict__ pred,
                       const float* __restrict__ gt,
                       const int*   __restrict__ x0,
                       const int*   __restrict__ y0,
                       float* __restrict__ out,
                       int n_corr, int W)
{
    const int warp = threadIdx.x >> 5;   // 0..3: which 8-row slab
    const int lane = threadIdx.x & 31;
    const int b = blockIdx.x;            // one patch per CTA

    __shared__ float sh[WARPS_PER_PATCH][5];

    const int X = x0[b] + warp * ROWS_PER_WARP;
    const int Y = y0[b];
    const float* __restrict__ pbase = pred + (size_t)X * W + Y + lane;
    const float* __restrict__ gbase = gt   + (size_t)X * W + Y + lane;

    float sp = 0.f, sg = 0.f, spp = 0.f, sgg = 0.f, spg = 0.f;

    // Single front-batch of 16 loads per lane (8 rows x {p,g}).
    float p[ROWS_PER_WARP], g[ROWS_PER_WARP];
    #pragma unroll
    for (int r = 0; r < ROWS_PER_WARP; r++) {
        const size_t off = (size_t)r * W;
        p[r] = __ldg(pbase + off);
        g[r] = __ldg(gbase + off);
    }
    #pragma unroll
    for (int r = 0; r < ROWS_PER_WARP; r++) {
        sp  += p[r];
        sg  += g[r];
        spp += p[r] * p[r];
        sgg += g[r] * g[r];
        spg += p[r] * g[r];
    }

    // Warp reduction of the 5 partial sums
    #pragma unroll
    for (int o = 16; o > 0; o >>= 1) {
        sp  += __shfl_down_sync(0xFFFFFFFFu, sp,  o);
        sg  += __shfl_down_sync(0xFFFFFFFFu, sg,  o);
        spp += __shfl_down_sync(0xFFFFFFFFu, spp, o);
        sgg += __shfl_down_sync(0xFFFFFFFFu, sgg, o);
        spg += __shfl_down_sync(0xFFFFFFFFu, spg, o);
    }

    if (lane == 0) {
        sh[warp][0] = sp;  sh[warp][1] = sg;  sh[warp][2] = spp;
        sh[warp][3] = sgg; sh[warp][4] = spg;
    }
    __syncthreads();

    if (threadIdx.x == 0) {
        float Sp = 0.f, Sg = 0.f, Spp = 0.f, Sgg = 0.f, Spg = 0.f;
        #pragma unroll
        for (int w = 0; w < WARPS_PER_PATCH; w++) {
            Sp  += sh[w][0];
            Sg  += sh[w][1];
            Spp += sh[w][2];
            Sgg += sh[w][3];
            Spg += sh[w][4];
        }

        const float P    = (float)PATCH_ELEMS;
        const float invP = 1.0f / P;
        const float mp = Sp * invP;
        const float mg = Sg * invP;
        // unbiased (ddof=1) variance, matching jnp.std(ddof=1)
        const float varp = (Spp - Sp * mp) / (P - 1.0f);
        const float varg = (Sgg - Sg * mg) / (P - 1.0f);
        const float sdp = sqrtf(fmaxf(varp, 0.f)) + EPSF;
        const float sdg = sqrtf(fmaxf(varg, 0.f)) + EPSF;
        const float cov = Spg - Sp * mg;   // = Spg - Sp*Sg/P
        const float co  = cov / (P * sdp * sdg);
        atomicAdd(out, (1.0f - co) / (float)n_corr);
    }
}

extern "C" void kernel_launch(void* const* d_in, const int* in_sizes, int n_in,
                              void* d_out, int out_size)
{
    const float* pred = (const float*)d_in[0];
    const float* gt   = (const float*)d_in[1];
    const int*   x0   = (const int*)d_in[2];
    const int*   y0   = (const int*)d_in[3];
    float* out = (float*)d_out;

    const int n_corr = in_sizes[2];

    // Derive W from the (square, C=1) image element count.
    int W = 1;
    while ((long long)W * W < (long long)in_sizes[0]) W <<= 1;

    lp_zero_out<<<1, 32>>>(out);
    lp_pearson_kernel<<<n_corr, THREADS>>>(pred, gt, x0, y0, out, n_corr, W);
}

// round 12
// speedup vs baseline: 1.4598x; 1.0062x over previous
#include <cuda_runtime.h>
#include <cuda_bf16.h>
#include <math.h>

#define BOX_P 32
#define PATCH_ELEMS (BOX_P * BOX_P)   // 1024
#define WARPS_PER_PATCH 4
#define ROWS_PER_WARP (BOX_P / WARPS_PER_PATCH)   // 8
#define THREADS (WARPS_PER_PATCH * 32)             // 128: one patch per CTA
#define EPSF 1e-6f

// Cross-CTA accumulator + completion counter.
// Invariant: both are 0 at kernel entry (zero at module load; the last CTA of
// every launch drains/resets them), so every call does identical work.
__device__ float        g_acc = 0.0f;
__device__ unsigned int g_cnt = 0u;

__global__ __launch_bounds__(THREADS)
void lp_pearson_kernel(const float* __restrict__ pred,
                       const float* __restrict__ gt,
                       const int*   __restrict__ x0,
                       const int*   __restrict__ y0,
                       float* __restrict__ out,
                       int n_corr, int W)
{
    const int warp = threadIdx.x >> 5;   // 0..3: which 8-row slab
    const int lane = threadIdx.x & 31;
    const int b = blockIdx.x;            // one patch per CTA

    __shared__ float sh[WARPS_PER_PATCH][5];

    const int X = x0[b] + warp * ROWS_PER_WARP;
    const int Y = y0[b];
    const float* __restrict__ pbase = pred + (size_t)X * W + Y + lane;
    const float* __restrict__ gbase = gt   + (size_t)X * W + Y + lane;

    float sp = 0.f, sg = 0.f, spp = 0.f, sgg = 0.f, spg = 0.f;

    // Single front-batch of 16 loads per lane (8 rows x {p,g}).
    float p[ROWS_PER_WARP], g[ROWS_PER_WARP];
    #pragma unroll
    for (int r = 0; r < ROWS_PER_WARP; r++) {
        const size_t off = (size_t)r * W;
        p[r] = __ldg(pbase + off);
        g[r] = __ldg(gbase + off);
    }
    #pragma unroll
    for (int r = 0; r < ROWS_PER_WARP; r++) {
        sp  += p[r];
        sg  += g[r];
        spp += p[r] * p[r];
        sgg += g[r] * g[r];
        spg += p[r] * g[r];
    }

    // Warp reduction of the 5 partial sums
    #pragma unroll
    for (int o = 16; o > 0; o >>= 1) {
        sp  += __shfl_down_sync(0xFFFFFFFFu, sp,  o);
        sg  += __shfl_down_sync(0xFFFFFFFFu, sg,  o);
        spp += __shfl_down_sync(0xFFFFFFFFu, spp, o);
        sgg += __shfl_down_sync(0xFFFFFFFFu, sgg, o);
        spg += __shfl_down_sync(0xFFFFFFFFu, spg, o);
    }

    if (lane == 0) {
        sh[warp][0] = sp;  sh[warp][1] = sg;  sh[warp][2] = spp;
        sh[warp][3] = sgg; sh[warp][4] = spg;
    }
    __syncthreads();

    if (threadIdx.x == 0) {
        float Sp = 0.f, Sg = 0.f, Spp = 0.f, Sgg = 0.f, Spg = 0.f;
        #pragma unroll
        for (int w = 0; w < WARPS_PER_PATCH; w++) {
            Sp  += sh[w][0];
            Sg  += sh[w][1];
            Spp += sh[w][2];
            Sgg += sh[w][3];
            Spg += sh[w][4];
        }

        const float P    = (float)PATCH_ELEMS;
        const float invP = 1.0f / P;
        const float mp = Sp * invP;
        const float mg = Sg * invP;
        // unbiased (ddof=1) variance, matching jnp.std(ddof=1)
        const float varp = (Spp - Sp * mp) / (P - 1.0f);
        const float varg = (Sgg - Sg * mg) / (P - 1.0f);
        const float sdp = sqrtf(fmaxf(varp, 0.f)) + EPSF;
        const float sdg = sqrtf(fmaxf(varg, 0.f)) + EPSF;
        const float cov = Spg - Sp * mg;   // = Spg - Sp*Sg/P
        const float co  = cov / (P * sdp * sdg);
        const float term = (1.0f - co) / (float)n_corr;

        // Fused finalization: accumulate, then last CTA drains to out[0]
        // and restores the zero-invariant for the next (graph-replayed) call.
        atomicAdd(&g_acc, term);
        __threadfence();
        const unsigned int done = atomicAdd(&g_cnt, 1u);
        if (done == (unsigned int)(gridDim.x - 1)) {
            out[0] = atomicExch(&g_acc, 0.0f);   // read total + reset
            atomicExch(&g_cnt, 0u);              // reset counter
        }
    }
}

extern "C" void kernel_launch(void* const* d_in, const int* in_sizes, int n_in,
                              void* d_out, int out_size)
{
    const float* pred = (const float*)d_in[0];
    const float* gt   = (const float*)d_in[1];
    const int*   x0   = (const int*)d_in[2];
    const int*   y0   = (const int*)d_in[3];
    float* out = (float*)d_out;

    const int n_corr = in_sizes[2];

    // Derive W from the (square, C=1) image element count.
    int W = 1;
    while ((long long)W * W < (long long)in_sizes[0]) W <<= 1;

    lp_pearson_kernel<<<n_corr, THREADS>>>(pred, gt, x0, y0, out, n_corr, W);
}